// round 2
// baseline (speedup 1.0000x reference)
#include <cuda_runtime.h>
#include <cuda_bf16.h>
#include <cstdint>

// Problem constants (from reference): B=8, N=2048, FEAT=16, pos = feats [0,2),
// radius = 0.25. Output [B, N, N] fp32 dense mask.
// NOTE: reference declares T/taus as jnp.int64, but JAX x64 is disabled by
// default, so the harness almost certainly materialized them as int32. We
// decode defensively: int64-with-small-values has zero odd words.
static constexpr int N_ = 2048;
static constexpr int J4_BITS = 9;   // N/4 = 512 float4 per row
static constexpr int I_BITS  = 11;  // N = 2048 rows
static constexpr float R2 = 0.0625f;  // 0.25^2

__device__ __forceinline__ int read_idx_arr(const int* __restrict__ a32, int b)
{
    // int64 layout (little-endian, small positive values): [v0, 0, v1, 0, ...]
    // int32 layout:                                        [v0, v1, v2, ...]
    const bool is64 = (a32[1] == 0) && (a32[0] != 0);
    return is64 ? a32[2 * b] : a32[b];
}

__global__ void __launch_bounds__(256)
radius_edge_kernel(const float* __restrict__ nodes,
                   const int* __restrict__ T_arr,
                   const int* __restrict__ tau_arr,
                   float4* __restrict__ out)
{
    const int idx = blockIdx.x * blockDim.x + threadIdx.x;

    // idx -> (b, i, j4); all pow-2 dims
    const int j4   = idx & ((1 << J4_BITS) - 1);
    const int rest = idx >> J4_BITS;
    const int i    = rest & ((1 << I_BITS) - 1);
    const int b    = rest >> I_BITS;

    const int Tlo = read_idx_arr(T_arr, b);
    const int Thi = Tlo + read_idx_arr(tau_arr, b);   // active columns: [Tlo, Thi)

    const int j0 = j4 << 2;

    float4 v = make_float4(0.f, 0.f, 0.f, 0.f);

    // Fast reject: whole float4 outside active window, or causality kills all 4.
    if (j0 + 3 >= Tlo && j0 < Thi && j0 + 3 > i) {
        const float* __restrict__ batch_base = nodes + (size_t)b * N_ * 16;
        const float2 pi = *(const float2*)(batch_base + (size_t)i * 16);

        #pragma unroll
        for (int k = 0; k < 4; k++) {
            const int j = j0 + k;
            if (j > i && j >= Tlo && j < Thi) {
                const float2 pj = *(const float2*)(batch_base + (size_t)j * 16);
                const float dx = pi.x - pj.x;
                const float dy = pi.y - pj.y;
                const float d2 = dx * dx + dy * dy;
                reinterpret_cast<float*>(&v)[k] = (d2 < R2) ? 1.0f : 0.0f;
            }
        }
    }

    out[idx] = v;   // coalesced 16B store, one store per output element
}

extern "C" void kernel_launch(void* const* d_in, const int* in_sizes, int n_in,
                              void* d_out, int out_size)
{
    const float* nodes   = (const float*)d_in[0];
    const int*   T_arr   = (const int*)d_in[1];
    const int*   tau_arr = (const int*)d_in[2];
    // d_in[3] = B scalar, unused (shapes are compile-time constants)

    float4* out = (float4*)d_out;
    const int total4 = out_size >> 2;          // 8,388,608 float4 stores
    const int threads = 256;
    const int blocks = (total4 + threads - 1) / threads;  // 32768

    radius_edge_kernel<<<blocks, threads>>>(nodes, T_arr, tau_arr, out);
}

// round 3
// speedup vs baseline: 1.5841x; 1.5841x over previous
#include <cuda_runtime.h>
#include <cuda_bf16.h>
#include <cstdint>

// B=8, N=2048, FEAT=16, pos = feats [0,2), radius = 0.25.
// Output [B, N, N] fp32 dense mask = 128 MiB -> compulsory store traffic;
// target is pure HBM-write-bound operation.
static constexpr int N_     = 2048;
static constexpr int BATCH_ = 8;
static constexpr int R_ROWS = 16;          // rows per block (register-reuse tile)
static constexpr float R2   = 0.0625f;     // 0.25^2

// Compacted positions: converts stride-64B gathers into dense coalesced reads.
__device__ __align__(16) float2 g_pos[BATCH_][N_];

__device__ __forceinline__ int read_idx_arr(const int* __restrict__ a32, int b)
{
    // Handles both int32 and int64(small values) materialization of T/taus.
    const bool is64 = (a32[1] == 0) && (a32[0] != 0);
    return is64 ? a32[2 * b] : a32[b];
}

__global__ void __launch_bounds__(256)
compact_kernel(const float* __restrict__ nodes)
{
    const int b = blockIdx.x;
    for (int j = threadIdx.x; j < N_; j += 256) {
        g_pos[b][j] = *(const float2*)(nodes + ((size_t)b * N_ + j) * 16);
    }
}

__global__ void __launch_bounds__(256)
radius_edge_kernel(const int* __restrict__ T_arr,
                   const int* __restrict__ tau_arr,
                   float4* __restrict__ out)
{
    // grid = B * (N / R_ROWS) = 8 * 128 = 1024 blocks
    const int b  = blockIdx.x >> 7;           // /128
    const int i0 = (blockIdx.x & 127) * R_ROWS;
    const int t  = threadIdx.x;

    const int Tlo = read_idx_arr(T_arr, b);
    const int Thi = Tlo + read_idx_arr(tau_arr, b);  // active cols [Tlo, Thi)

    // Each thread owns two float4 output groups per row: j4 = t and t+256.
    const int j0a = 4 * t;
    const int j0b = 4 * (t + 256);

    // Load the 8 column positions ONCE (coalesced float4 loads), reuse x16 rows.
    const float4* pbase = reinterpret_cast<const float4*>(&g_pos[b][0]);
    const float4 ra0 = pbase[2 * t];
    const float4 ra1 = pbase[2 * t + 1];
    const float4 rb0 = pbase[2 * (t + 256)];
    const float4 rb1 = pbase[2 * (t + 256) + 1];

    float pax[4] = {ra0.x, ra0.z, ra1.x, ra1.z};
    float pay[4] = {ra0.y, ra0.w, ra1.y, ra1.w};
    float pbx[4] = {rb0.x, rb0.z, rb1.x, rb1.z};
    float pby[4] = {rb0.y, rb0.w, rb1.y, rb1.w};

    // Loop-invariant window masks.
    bool wa[4], wb[4];
    #pragma unroll
    for (int k = 0; k < 4; k++) {
        wa[k] = (j0a + k >= Tlo) && (j0a + k < Thi);
        wb[k] = (j0b + k >= Tlo) && (j0b + k < Thi);
    }

    float4* orow = out + ((size_t)b * N_ + i0) * (N_ / 4);

    #pragma unroll 4
    for (int r = 0; r < R_ROWS; r++) {
        const int i = i0 + r;
        const float2 pi = g_pos[b][i];   // uniform -> broadcast load

        float4 va, vb;
        #pragma unroll
        for (int k = 0; k < 4; k++) {
            float dx = pi.x - pax[k];
            float dy = pi.y - pay[k];
            bool  c  = wa[k] & (i < j0a + k) & (fmaf(dx, dx, dy * dy) < R2);
            (&va.x)[k] = c ? 1.0f : 0.0f;

            dx = pi.x - pbx[k];
            dy = pi.y - pby[k];
            c  = wb[k] & (i < j0b + k) & (fmaf(dx, dx, dy * dy) < R2);
            (&vb.x)[k] = c ? 1.0f : 0.0f;
        }

        orow[(size_t)r * (N_ / 4) + t]       = va;   // coalesced 4KB/warp-group
        orow[(size_t)r * (N_ / 4) + t + 256] = vb;
    }
}

extern "C" void kernel_launch(void* const* d_in, const int* in_sizes, int n_in,
                              void* d_out, int out_size)
{
    const float* nodes   = (const float*)d_in[0];
    const int*   T_arr   = (const int*)d_in[1];
    const int*   tau_arr = (const int*)d_in[2];
    // d_in[3] = B scalar, unused (compile-time constants)

    compact_kernel<<<BATCH_, 256>>>(nodes);

    const int blocks = BATCH_ * (N_ / R_ROWS);   // 1024
    radius_edge_kernel<<<blocks, 256>>>(T_arr, tau_arr, (float4*)d_out);
}

// round 5
// speedup vs baseline: 1.7423x; 1.0999x over previous
#include <cuda_runtime.h>
#include <cuda_bf16.h>
#include <cstdint>

// B=8, N=2048, FEAT=16, pos = feats [0,2), radius = 0.25.
// Output [B, N, N] fp32 mask = 128 MiB compulsory stores -> HBM-write-bound target.
static constexpr int N_     = 2048;
static constexpr int BATCH_ = 8;
static constexpr int R_ROWS = 16;          // rows per block (register-reuse tile)
static constexpr float R2   = 0.0625f;     // 0.25^2

// Compacted positions: dense float2, so main-kernel reads are coalesced.
__device__ __align__(16) float2 g_pos[BATCH_][N_];

__device__ __forceinline__ int read_idx_arr(const int* __restrict__ a32, int b)
{
    // Handles both int32 and int64(small values) materialization of T/taus.
    const bool is64 = (a32[1] == 0) && (a32[0] != 0);
    return is64 ? a32[2 * b] : a32[b];
}

// Coalesced compaction. Each warp handles 32 consecutive nodes:
// phase 1: 32 lanes read the 32 nodes' first float4 (stride 64B covered by
//          4-way sectors, fully pipelined), phase 2: coalesced float2 store.
__global__ void __launch_bounds__(256)
compact_kernel(const float* __restrict__ nodes)
{
    const int node = blockIdx.x * 256 + threadIdx.x;   // 64 blocks x 256 = 16384
    const float2 p = *(const float2*)(nodes + (size_t)node * 16);
    reinterpret_cast<float2*>(g_pos)[node] = p;        // coalesced 8B store
}

__global__ void __launch_bounds__(512, 3)
radius_edge_kernel(const int* __restrict__ T_arr,
                   const int* __restrict__ tau_arr,
                   float4* __restrict__ out)
{
    // grid = B * (N / R_ROWS) = 1024 blocks x 512 threads
    const int b  = blockIdx.x >> 7;            // /128
    const int i0 = (blockIdx.x & 127) * R_ROWS;
    const int t  = threadIdx.x;                // one float4 column-group each

    const int Tlo = read_idx_arr(T_arr, b);
    const int Thi = Tlo + read_idx_arr(tau_arr, b);  // active cols [Tlo, Thi)

    const int j0 = 4 * t;

    // Load this thread's 4 column positions ONCE (two coalesced LDG.128),
    // reuse across all 16 rows.
    const float4* pbase = reinterpret_cast<const float4*>(&g_pos[b][0]);
    const float4 r0 = pbase[2 * t];
    const float4 r1 = pbase[2 * t + 1];
    const float px[4] = {r0.x, r0.z, r1.x, r1.z};
    const float py[4] = {r0.y, r0.w, r1.y, r1.w};

    // Loop-invariant column-window mask.
    bool w[4];
    #pragma unroll
    for (int k = 0; k < 4; k++)
        w[k] = (j0 + k >= Tlo) && (j0 + k < Thi);

    float4* orow = out + ((size_t)b * N_ + i0) * (N_ / 4) + t;

    #pragma unroll 4
    for (int r = 0; r < R_ROWS; r++) {
        const int i = i0 + r;
        const float2 pi = g_pos[b][i];   // uniform -> broadcast load (L1 hit)

        float4 v;
        #pragma unroll
        for (int k = 0; k < 4; k++) {
            const float dx = pi.x - px[k];
            const float dy = pi.y - py[k];
            const bool  c  = w[k] & (i < j0 + k) & (fmaf(dx, dx, dy * dy) < R2);
            (&v.x)[k] = c ? 1.0f : 0.0f;
        }
        orow[(size_t)r * (N_ / 4)] = v;   // coalesced 8KB per block-row
    }
}

extern "C" void kernel_launch(void* const* d_in, const int* in_sizes, int n_in,
                              void* d_out, int out_size)
{
    const float* nodes   = (const float*)d_in[0];
    const int*   T_arr   = (const int*)d_in[1];
    const int*   tau_arr = (const int*)d_in[2];
    // d_in[3] = B scalar, unused (compile-time constants)

    compact_kernel<<<64, 256>>>(nodes);        // 16384 nodes, 1 thread each

    const int blocks = BATCH_ * (N_ / R_ROWS); // 1024
    radius_edge_kernel<<<blocks, 512>>>(T_arr, tau_arr, (float4*)d_out);
}